// round 1
// baseline (speedup 1.0000x reference)
#include <cuda_runtime.h>
#include <cuda_bf16.h>
#include <cstdint>

// Problem constants (derived at runtime where possible; buffers sized for max)
#define MAXN 100352
#define MAXE 1703936
#define D_OUT 64          // H*C
#define NEG_SLOPE 0.2f

// ---------------- scratch (static device allocations) ----------------
__device__ float g_xl[(size_t)MAXN * D_OUT];
__device__ float g_xr[(size_t)MAXN * D_OUT];
__device__ float g_h [(size_t)MAXN * D_OUT];
__device__ int   g_deg[MAXN];
__device__ int   g_rowptr[MAXN + 1];
__device__ int   g_cursor[MAXN];
__device__ int   g_srcs[MAXE];
__device__ int   g_bsum[1024];

// ---------------- CSR build ----------------
__global__ void k_count(const int* __restrict__ ei, int* __restrict__ deg,
                        int E, int ET) {
    int e = blockIdx.x * blockDim.x + threadIdx.x;
    if (e >= ET) return;
    int dst = (e < E) ? ei[E + e] : (e - E);
    atomicAdd(&deg[dst], 1);
}

__global__ void k_scanA(const int* __restrict__ deg, int* __restrict__ rowptr,
                        int* __restrict__ bsum, int n) {
    __shared__ int sh[1024];
    int t = threadIdx.x;
    int i = blockIdx.x * 1024 + t;
    int v = (i < n) ? deg[i] : 0;
    sh[t] = v;
    __syncthreads();
    #pragma unroll
    for (int off = 1; off < 1024; off <<= 1) {
        int u = (t >= off) ? sh[t - off] : 0;
        __syncthreads();
        sh[t] += u;
        __syncthreads();
    }
    if (i < n) rowptr[i] = sh[t] - v;   // local exclusive
    if (t == 1023) bsum[blockIdx.x] = sh[t];
}

__global__ void k_scanB(int* __restrict__ bsum, int nb) {
    __shared__ int sh[1024];
    int t = threadIdx.x;
    int v = (t < nb) ? bsum[t] : 0;
    sh[t] = v;
    __syncthreads();
    #pragma unroll
    for (int off = 1; off < 1024; off <<= 1) {
        int u = (t >= off) ? sh[t - off] : 0;
        __syncthreads();
        sh[t] += u;
        __syncthreads();
    }
    if (t < nb) bsum[t] = sh[t] - v;    // exclusive
}

__global__ void k_scanC(int* __restrict__ rowptr, int* __restrict__ cursor,
                        const int* __restrict__ bsum, int n, int etot) {
    int i = blockIdx.x * 1024 + threadIdx.x;
    if (i < n) {
        int r = rowptr[i] + bsum[blockIdx.x];
        rowptr[i] = r;
        cursor[i] = r;
    }
    if (i == 0) rowptr[n] = etot;
}

__global__ void k_scatter(const int* __restrict__ ei, int* __restrict__ cursor,
                          int* __restrict__ srcs, int E, int ET) {
    int e = blockIdx.x * blockDim.x + threadIdx.x;
    if (e >= ET) return;
    int src, dst;
    if (e < E) { src = ei[e]; dst = ei[E + e]; }
    else       { src = dst = e - E; }
    int pos = atomicAdd(&cursor[dst], 1);
    srcs[pos] = src;
}

// ---------------- fused dual GEMM: xl = X*Wl, xr = X*Wr ----------------
// Block: 256 threads = 8 warps; each warp handles 4 nodes x (lane: 4 cols of 128).
// W (K x 128, Wl||Wr) cached in smem; x rows in smem (broadcast reads).
template <int K>
__global__ void k_gemm(const float* __restrict__ X, const float* __restrict__ Wl,
                       const float* __restrict__ Wr, float* __restrict__ xl,
                       float* __restrict__ xr, int N) {
    extern __shared__ float sm[];
    float* Wsh = sm;            // [K][128]
    float* xs  = sm + K * 128;  // [32][K]
    int tid = threadIdx.x;

    for (int i = tid; i < K * 64; i += 256) {
        int k = i >> 6, j = i & 63;
        Wsh[k * 128 + j]      = Wl[i];
        Wsh[k * 128 + 64 + j] = Wr[i];
    }

    int base = blockIdx.x * 32;
    for (int i = tid; i < 32 * K; i += 256) {
        int node = base + i / K;
        // write after the W loop's __syncthreads-free region: xs disjoint from Wsh
        xs[i] = (node < N) ? X[(size_t)node * K + (i % K)] : 0.f;
    }
    __syncthreads();

    int warp = tid >> 5, lane = tid & 31;
    int colb = lane * 4;
    const float* xrow = xs + warp * 4 * K;

    float4 a0 = make_float4(0.f, 0.f, 0.f, 0.f), a1 = a0, a2 = a0, a3 = a0;
    #pragma unroll 8
    for (int k = 0; k < K; k++) {
        float4 w4 = *(const float4*)&Wsh[k * 128 + colb];
        float x0 = xrow[k];
        float x1 = xrow[K + k];
        float x2 = xrow[2 * K + k];
        float x3 = xrow[3 * K + k];
        a0.x += x0 * w4.x; a0.y += x0 * w4.y; a0.z += x0 * w4.z; a0.w += x0 * w4.w;
        a1.x += x1 * w4.x; a1.y += x1 * w4.y; a1.z += x1 * w4.z; a1.w += x1 * w4.w;
        a2.x += x2 * w4.x; a2.y += x2 * w4.y; a2.z += x2 * w4.z; a2.w += x2 * w4.w;
        a3.x += x3 * w4.x; a3.y += x3 * w4.y; a3.z += x3 * w4.z; a3.w += x3 * w4.w;
    }

    float4 accs[4] = {a0, a1, a2, a3};
    #pragma unroll
    for (int r = 0; r < 4; r++) {
        int node = base + warp * 4 + r;
        if (node < N) {
            if (colb < 64)
                *(float4*)&xl[(size_t)node * 64 + colb] = accs[r];
            else
                *(float4*)&xr[(size_t)node * 64 + colb - 64] = accs[r];
        }
    }
}

// ---------------- fused edge softmax + aggregation (warp per dst node) ----
// For each incoming edge: logit = sum_c LeakyReLU(xl[s]+xr[d]) * att  (per head),
// p = exp(logit) [no max-subtraction needed: logits are O(10)], accumulate
// unnormalized sum and Sigma p in registers; normalize + bias + relu at end.
__global__ void k_agg(const float* __restrict__ xl, const float* __restrict__ xr,
                      const int* __restrict__ rowptr, const int* __restrict__ srcs,
                      const float* __restrict__ att, const float* __restrict__ bias,
                      float* __restrict__ out, int N) {
    int wg   = (blockIdx.x * blockDim.x + threadIdx.x) >> 5;  // dst node
    int lane = threadIdx.x & 31;
    if (wg >= N) return;

    // lane covers feature elems 2*lane, 2*lane+1; head = lane/8
    float2 xr2 = *(const float2*)&xr[(size_t)wg * 64 + lane * 2];
    float2 at2 = *(const float2*)&att[(lane >> 3) * 16 + (lane & 7) * 2];

    int e0 = rowptr[wg], e1 = rowptr[wg + 1];
    float accx = 0.f, accy = 0.f, ps = 0.f;

    int s = (e0 < e1) ? srcs[e0] : 0;
    for (int e = e0; e < e1; e++) {
        int snext = (e + 1 < e1) ? srcs[e + 1] : 0;
        float2 v = *(const float2*)&xl[(size_t)s * 64 + lane * 2];
        float tx = v.x + xr2.x, ty = v.y + xr2.y;
        tx = fmaxf(tx, 0.f) + NEG_SLOPE * fminf(tx, 0.f);
        ty = fmaxf(ty, 0.f) + NEG_SLOPE * fminf(ty, 0.f);
        float l = tx * at2.x + ty * at2.y;
        l += __shfl_xor_sync(0xFFFFFFFFu, l, 1);
        l += __shfl_xor_sync(0xFFFFFFFFu, l, 2);
        l += __shfl_xor_sync(0xFFFFFFFFu, l, 4);
        float p = __expf(l);
        ps   += p;
        accx += v.x * p;
        accy += v.y * p;
        s = snext;
    }

    float2 b2 = *(const float2*)&bias[lane * 2];
    float inv = 1.f / ps;   // ps > 0: every node has a self-loop
    float ox = fmaxf(accx * inv + b2.x, 0.f);
    float oy = fmaxf(accy * inv + b2.y, 0.f);
    *(float2*)&out[(size_t)wg * 64 + lane * 2] = make_float2(ox, oy);
}

// ---------------- launch ----------------
extern "C" void kernel_launch(void* const* d_in, const int* in_sizes, int n_in,
                              void* d_out, int out_size) {
    const float* x    = (const float*)d_in[0];
    const int*   ei   = (const int*)  d_in[1];
    const float* W1l  = (const float*)d_in[2];
    const float* W1r  = (const float*)d_in[3];
    const float* att1 = (const float*)d_in[4];
    const float* b1   = (const float*)d_in[5];
    const float* W2l  = (const float*)d_in[6];
    const float* W2r  = (const float*)d_in[7];
    const float* att2 = (const float*)d_in[8];
    const float* b2   = (const float*)d_in[9];

    int F  = in_sizes[2] / D_OUT;     // 128
    int N  = in_sizes[0] / F;         // 100000
    int E  = in_sizes[1] / 2;         // 1600000
    int ET = E + N;                   // with self-loops
    if (N > MAXN || ET > MAXE || F != 128) return;

    void *p_xl, *p_xr, *p_h, *p_deg, *p_rp, *p_cur, *p_src, *p_bs;
    cudaGetSymbolAddress(&p_xl,  g_xl);
    cudaGetSymbolAddress(&p_xr,  g_xr);
    cudaGetSymbolAddress(&p_h,   g_h);
    cudaGetSymbolAddress(&p_deg, g_deg);
    cudaGetSymbolAddress(&p_rp,  g_rowptr);
    cudaGetSymbolAddress(&p_cur, g_cursor);
    cudaGetSymbolAddress(&p_src, g_srcs);
    cudaGetSymbolAddress(&p_bs,  g_bsum);

    float* xl   = (float*)p_xl;
    float* xr   = (float*)p_xr;
    float* hbuf = (float*)p_h;
    int* deg    = (int*)p_deg;
    int* rp     = (int*)p_rp;
    int* cur    = (int*)p_cur;
    int* srcs   = (int*)p_src;
    int* bs     = (int*)p_bs;

    // smem sizes for the two GEMM instantiations
    size_t smem128 = (size_t)128 * 128 * 4 + 32 * 128 * 4;  // 80 KB
    size_t smem64  = (size_t)64  * 128 * 4 + 32 * 64  * 4;  // 40 KB
    cudaFuncSetAttribute(k_gemm<128>, cudaFuncAttributeMaxDynamicSharedMemorySize,
                         (int)smem128);
    cudaFuncSetAttribute(k_gemm<64>, cudaFuncAttributeMaxDynamicSharedMemorySize,
                         (int)smem64);

    // ---- CSR build (dst-grouped), shared by both layers ----
    cudaMemsetAsync(deg, 0, (size_t)N * sizeof(int));
    int nbE = (ET + 255) / 256;
    k_count<<<nbE, 256>>>(ei, deg, E, ET);
    int NB = (N + 1023) / 1024;
    k_scanA<<<NB, 1024>>>(deg, rp, bs, N);
    k_scanB<<<1, 1024>>>(bs, NB);
    k_scanC<<<NB, 1024>>>(rp, cur, bs, N, ET);
    k_scatter<<<nbE, 256>>>(ei, cur, srcs, E, ET);

    int gemmBlocks = (N + 31) / 32;
    int aggBlocks  = (N * 32 + 255) / 256;

    // ---- layer 1 ----
    k_gemm<128><<<gemmBlocks, 256, smem128>>>(x, W1l, W1r, xl, xr, N);
    k_agg<<<aggBlocks, 256>>>(xl, xr, rp, srcs, att1, b1, hbuf, N);

    // ---- layer 2 ----
    k_gemm<64><<<gemmBlocks, 256, smem64>>>(hbuf, W2l, W2r, xl, xr, N);
    k_agg<<<aggBlocks, 256>>>(xl, xr, rp, srcs, att2, b2, (float*)d_out, N);
}

// round 2
// speedup vs baseline: 1.1943x; 1.1943x over previous
#include <cuda_runtime.h>
#include <cuda_bf16.h>
#include <cstdint>

#define MAXN 100352
#define MAXE 1703936
#define D_OUT 64
#define NEG_SLOPE 0.2f

// ---------------- scratch ----------------
__device__ float g_xl[(size_t)MAXN * D_OUT];
__device__ float g_xr[(size_t)MAXN * D_OUT];
__device__ float g_h [(size_t)MAXN * D_OUT];
__device__ int   g_deg[MAXN];
__device__ int   g_rowptr[MAXN + 1];
__device__ int   g_cursor[MAXN];
__device__ int   g_srcs[MAXE];
__device__ int   g_bsum[1024];

// ---------------- packed f32x2 helpers ----------------
__device__ __forceinline__ unsigned long long pack2(float x) {
    unsigned long long r;
    asm("mov.b64 %0, {%1, %1};" : "=l"(r) : "f"(x));
    return r;
}
__device__ __forceinline__ void fma2(unsigned long long& d,
                                     unsigned long long a,
                                     unsigned long long b) {
    asm("fma.rn.f32x2 %0, %1, %2, %0;" : "+l"(d) : "l"(a), "l"(b));
}

// ---------------- CSR build ----------------
__global__ void k_count(const int* __restrict__ ei, int* __restrict__ deg,
                        int E, int ET) {
    int e = blockIdx.x * blockDim.x + threadIdx.x;
    if (e >= ET) return;
    int dst = (e < E) ? ei[E + e] : (e - E);
    atomicAdd(&deg[dst], 1);
}

__global__ void k_scanA(const int* __restrict__ deg, int* __restrict__ rowptr,
                        int* __restrict__ bsum, int n) {
    __shared__ int sh[1024];
    int t = threadIdx.x;
    int i = blockIdx.x * 1024 + t;
    int v = (i < n) ? deg[i] : 0;
    sh[t] = v;
    __syncthreads();
    #pragma unroll
    for (int off = 1; off < 1024; off <<= 1) {
        int u = (t >= off) ? sh[t - off] : 0;
        __syncthreads();
        sh[t] += u;
        __syncthreads();
    }
    if (i < n) rowptr[i] = sh[t] - v;   // local exclusive
    if (t == 1023) bsum[blockIdx.x] = sh[t];
}

// fused: each block computes its own bsum prefix (NB <= 1024, cheap)
__global__ void k_scanC2(int* __restrict__ rowptr, int* __restrict__ cursor,
                         const int* __restrict__ bsum, int n, int etot) {
    __shared__ int soff;
    int t = threadIdx.x;
    if (t < 32) {
        int s = 0;
        for (int i = t; i < blockIdx.x; i += 32) s += bsum[i];
        #pragma unroll
        for (int o = 16; o; o >>= 1) s += __shfl_xor_sync(0xFFFFFFFFu, s, o);
        if (t == 0) soff = s;
    }
    __syncthreads();
    int i = blockIdx.x * 1024 + t;
    if (i < n) {
        int r = rowptr[i] + soff;
        rowptr[i] = r;
        cursor[i] = r;
    }
    if (i == 0) rowptr[n] = etot;
}

__global__ void k_scatter(const int* __restrict__ ei, int* __restrict__ cursor,
                          int* __restrict__ srcs, int E, int ET) {
    int e = blockIdx.x * blockDim.x + threadIdx.x;
    if (e >= ET) return;
    int src, dst;
    if (e < E) { src = ei[e]; dst = ei[E + e]; }
    else       { src = dst = e - E; }
    int pos = atomicAdd(&cursor[dst], 1);
    srcs[pos] = src;
}

// ---------------- dual GEMM with packed f32x2 FMA ----------------
// Block: 256 thr = 8 warps, 64 nodes per block (8 rows per warp).
// Warp layout: lanes 0-15 -> rows r0..r3, cols (lane&15)*8..+7
//              lanes 16-31 -> rows r4..r7, same cols.
template <int K>
__global__ void k_gemm(const float* __restrict__ X, const float* __restrict__ Wl,
                       const float* __restrict__ Wr, float* __restrict__ xl,
                       float* __restrict__ xr, int N) {
    extern __shared__ float sm[];
    float* Wsh = sm;                 // [K][128]
    float* xs  = sm + K * 128;       // [64][K+1] padded
    const int KP = K + 1;
    int tid = threadIdx.x;

    for (int i = tid; i < K * 64; i += 256) {
        int k = i >> 6, j = i & 63;
        Wsh[k * 128 + j]      = Wl[i];
        Wsh[k * 128 + 64 + j] = Wr[i];
    }

    int base = blockIdx.x * 64;
    for (int i = tid; i < 64 * K; i += 256) {
        int r = i / K, c = i % K;
        int node = base + r;
        xs[r * KP + c] = (node < N) ? X[(size_t)node * K + c] : 0.f;
    }
    __syncthreads();

    int warp = tid >> 5, lane = tid & 31;
    int half = lane >> 4, cl = lane & 15;
    int colb = cl * 8;
    const float* xrow = xs + (warp * 8 + half * 4) * KP;

    unsigned long long acc[4][4];
    #pragma unroll
    for (int r = 0; r < 4; r++)
        #pragma unroll
        for (int p = 0; p < 4; p++) acc[r][p] = 0ull;

    #pragma unroll 4
    for (int k = 0; k < K; k++) {
        unsigned long long xp0 = pack2(xrow[k]);
        unsigned long long xp1 = pack2(xrow[KP + k]);
        unsigned long long xp2 = pack2(xrow[2 * KP + k]);
        unsigned long long xp3 = pack2(xrow[3 * KP + k]);
        ulonglong2 wa = *(const ulonglong2*)&Wsh[k * 128 + colb];
        ulonglong2 wb = *(const ulonglong2*)&Wsh[k * 128 + colb + 4];
        fma2(acc[0][0], xp0, wa.x); fma2(acc[0][1], xp0, wa.y);
        fma2(acc[0][2], xp0, wb.x); fma2(acc[0][3], xp0, wb.y);
        fma2(acc[1][0], xp1, wa.x); fma2(acc[1][1], xp1, wa.y);
        fma2(acc[1][2], xp1, wb.x); fma2(acc[1][3], xp1, wb.y);
        fma2(acc[2][0], xp2, wa.x); fma2(acc[2][1], xp2, wa.y);
        fma2(acc[2][2], xp2, wb.x); fma2(acc[2][3], xp2, wb.y);
        fma2(acc[3][0], xp3, wa.x); fma2(acc[3][1], xp3, wa.y);
        fma2(acc[3][2], xp3, wb.x); fma2(acc[3][3], xp3, wb.y);
    }

    #pragma unroll
    for (int r = 0; r < 4; r++) {
        int node = base + warp * 8 + half * 4 + r;
        if (node < N) {
            float* dst = (colb < 64) ? &xl[(size_t)node * 64 + colb]
                                     : &xr[(size_t)node * 64 + colb - 64];
            ulonglong2 lo; lo.x = acc[r][0]; lo.y = acc[r][1];
            ulonglong2 hi; hi.x = acc[r][2]; hi.y = acc[r][3];
            *(ulonglong2*)dst       = lo;
            *(ulonglong2*)(dst + 4) = hi;
        }
    }
}

// ---------------- fused edge softmax + aggregation ----------------
// warp per dst node; lane-coalesced src index loads, 2-edge unroll for ILP.
__global__ void k_agg(const float* __restrict__ xl, const float* __restrict__ xr,
                      const int* __restrict__ rowptr, const int* __restrict__ srcs,
                      const float* __restrict__ att, const float* __restrict__ bias,
                      float* __restrict__ out, int N) {
    int node = (blockIdx.x * blockDim.x + threadIdx.x) >> 5;
    int lane = threadIdx.x & 31;
    if (node >= N) return;

    float2 xr2 = *(const float2*)&xr[(size_t)node * 64 + lane * 2];
    float2 at2 = *(const float2*)&att[(lane >> 3) * 16 + (lane & 7) * 2];

    int e0 = rowptr[node], e1 = rowptr[node + 1];
    float accx = 0.f, accy = 0.f, ps = 0.f;

    for (int basee = e0; basee < e1; basee += 32) {
        int idx = basee + lane;
        int sv = (idx < e1) ? srcs[idx] : 0;
        int cnt = min(32, e1 - basee);
        int j = 0;
        for (; j + 1 < cnt; j += 2) {
            int s0 = __shfl_sync(0xFFFFFFFFu, sv, j);
            int s1 = __shfl_sync(0xFFFFFFFFu, sv, j + 1);
            float2 v0 = *(const float2*)&xl[(size_t)s0 * 64 + lane * 2];
            float2 v1 = *(const float2*)&xl[(size_t)s1 * 64 + lane * 2];
            float tx0 = v0.x + xr2.x, ty0 = v0.y + xr2.y;
            float tx1 = v1.x + xr2.x, ty1 = v1.y + xr2.y;
            tx0 = fmaxf(tx0, 0.f) + NEG_SLOPE * fminf(tx0, 0.f);
            ty0 = fmaxf(ty0, 0.f) + NEG_SLOPE * fminf(ty0, 0.f);
            tx1 = fmaxf(tx1, 0.f) + NEG_SLOPE * fminf(tx1, 0.f);
            ty1 = fmaxf(ty1, 0.f) + NEG_SLOPE * fminf(ty1, 0.f);
            float l0 = tx0 * at2.x + ty0 * at2.y;
            float l1 = tx1 * at2.x + ty1 * at2.y;
            l0 += __shfl_xor_sync(0xFFFFFFFFu, l0, 1);
            l1 += __shfl_xor_sync(0xFFFFFFFFu, l1, 1);
            l0 += __shfl_xor_sync(0xFFFFFFFFu, l0, 2);
            l1 += __shfl_xor_sync(0xFFFFFFFFu, l1, 2);
            l0 += __shfl_xor_sync(0xFFFFFFFFu, l0, 4);
            l1 += __shfl_xor_sync(0xFFFFFFFFu, l1, 4);
            float p0 = __expf(l0);
            float p1 = __expf(l1);
            ps   += p0;        ps   += p1;
            accx += v0.x * p0; accx += v1.x * p1;
            accy += v0.y * p0; accy += v1.y * p1;
        }
        if (j < cnt) {
            int s0 = __shfl_sync(0xFFFFFFFFu, sv, j);
            float2 v0 = *(const float2*)&xl[(size_t)s0 * 64 + lane * 2];
            float tx0 = v0.x + xr2.x, ty0 = v0.y + xr2.y;
            tx0 = fmaxf(tx0, 0.f) + NEG_SLOPE * fminf(tx0, 0.f);
            ty0 = fmaxf(ty0, 0.f) + NEG_SLOPE * fminf(ty0, 0.f);
            float l0 = tx0 * at2.x + ty0 * at2.y;
            l0 += __shfl_xor_sync(0xFFFFFFFFu, l0, 1);
            l0 += __shfl_xor_sync(0xFFFFFFFFu, l0, 2);
            l0 += __shfl_xor_sync(0xFFFFFFFFu, l0, 4);
            float p0 = __expf(l0);
            ps += p0; accx += v0.x * p0; accy += v0.y * p0;
        }
    }

    float2 b2 = *(const float2*)&bias[lane * 2];
    float inv = 1.f / ps;
    float ox = fmaxf(accx * inv + b2.x, 0.f);
    float oy = fmaxf(accy * inv + b2.y, 0.f);
    *(float2*)&out[(size_t)node * 64 + lane * 2] = make_float2(ox, oy);
}

// ---------------- launch ----------------
extern "C" void kernel_launch(void* const* d_in, const int* in_sizes, int n_in,
                              void* d_out, int out_size) {
    const float* x    = (const float*)d_in[0];
    const int*   ei   = (const int*)  d_in[1];
    const float* W1l  = (const float*)d_in[2];
    const float* W1r  = (const float*)d_in[3];
    const float* att1 = (const float*)d_in[4];
    const float* b1   = (const float*)d_in[5];
    const float* W2l  = (const float*)d_in[6];
    const float* W2r  = (const float*)d_in[7];
    const float* att2 = (const float*)d_in[8];
    const float* b2   = (const float*)d_in[9];

    int F  = in_sizes[2] / D_OUT;     // 128
    int N  = in_sizes[0] / F;         // 100000
    int E  = in_sizes[1] / 2;         // 1600000
    int ET = E + N;
    if (N > MAXN || ET > MAXE || F != 128) return;

    void *p_xl, *p_xr, *p_h, *p_deg, *p_rp, *p_cur, *p_src, *p_bs;
    cudaGetSymbolAddress(&p_xl,  g_xl);
    cudaGetSymbolAddress(&p_xr,  g_xr);
    cudaGetSymbolAddress(&p_h,   g_h);
    cudaGetSymbolAddress(&p_deg, g_deg);
    cudaGetSymbolAddress(&p_rp,  g_rowptr);
    cudaGetSymbolAddress(&p_cur, g_cursor);
    cudaGetSymbolAddress(&p_src, g_srcs);
    cudaGetSymbolAddress(&p_bs,  g_bsum);

    float* xl   = (float*)p_xl;
    float* xr   = (float*)p_xr;
    float* hbuf = (float*)p_h;
    int* deg    = (int*)p_deg;
    int* rp     = (int*)p_rp;
    int* cur    = (int*)p_cur;
    int* srcs   = (int*)p_src;
    int* bs     = (int*)p_bs;

    size_t smem128 = (size_t)128 * 128 * 4 + (size_t)64 * 129 * 4;  // ~97.3 KB
    size_t smem64  = (size_t)64  * 128 * 4 + (size_t)64 * 65  * 4;  // ~48.9 KB
    cudaFuncSetAttribute(k_gemm<128>, cudaFuncAttributeMaxDynamicSharedMemorySize,
                         (int)smem128);
    cudaFuncSetAttribute(k_gemm<64>, cudaFuncAttributeMaxDynamicSharedMemorySize,
                         (int)smem64);

    // ---- CSR build ----
    cudaMemsetAsync(deg, 0, (size_t)N * sizeof(int));
    int nbE = (ET + 255) / 256;
    k_count<<<nbE, 256>>>(ei, deg, E, ET);
    int NB = (N + 1023) / 1024;
    k_scanA<<<NB, 1024>>>(deg, rp, bs, N);
    k_scanC2<<<NB, 1024>>>(rp, cur, bs, N, ET);
    k_scatter<<<nbE, 256>>>(ei, cur, srcs, E, ET);

    int gemmBlocks = (N + 63) / 64;
    int aggBlocks  = (N + 7) / 8;

    // ---- layer 1 ----
    k_gemm<128><<<gemmBlocks, 256, smem128>>>(x, W1l, W1r, xl, xr, N);
    k_agg<<<aggBlocks, 256>>>(xl, xr, rp, srcs, att1, b1, hbuf, N);

    // ---- layer 2 ----
    k_gemm<64><<<gemmBlocks, 256, smem64>>>(hbuf, W2l, W2r, xl, xr, N);
    k_agg<<<aggBlocks, 256>>>(xl, xr, rp, srcs, att2, b2, (float*)d_out, N);
}